// round 7
// baseline (speedup 1.0000x reference)
#include <cuda_runtime.h>
#include <cuda_bf16.h>

#define NNODES 50000
#define HIDDEN 128
#define MLPD   64
#define SE_STRIDE 132   // padded row stride (floats); 132 % 8 == 4 -> bank-safe

// Per-node precomputed table:
//   T[n][0:64]   = emb[n] @ W1[0:128,:]  + b1   (src half, bias folded in)
//   T[n][64:128] = emb[n] @ W1[128:256,:]       (dst half)
__device__ float g_T[(size_t)NNODES * HIDDEN];
__device__ int g_is64;   // 1 if edge_index buffer is int64, 0 if int32

// ---- packed f32x2 helpers (sm_100+ only via PTX) ---------------------------
__device__ __forceinline__ unsigned long long pk2(float lo, float hi) {
    unsigned long long r;
    asm("mov.b64 %0, {%1,%2};" : "=l"(r) : "f"(lo), "f"(hi));
    return r;
}
__device__ __forceinline__ unsigned long long fma2(unsigned long long a,
                                                   unsigned long long b,
                                                   unsigned long long c) {
    unsigned long long d;
    asm("fma.rn.f32x2 %0, %1, %2, %3;" : "=l"(d) : "l"(a), "l"(b), "l"(c));
    return d;
}
__device__ __forceinline__ void upk2(unsigned long long v, float& lo, float& hi) {
    asm("mov.b64 {%0,%1}, %2;" : "=f"(lo), "=f"(hi) : "l"(v));
}

// ---------------------------------------------------------------------------
// Kernel 1: T = emb @ Wc (+b1 on cols 0..63)
//   Wc[k][c] = (c<64) ? W1[k][c] : W1[128+k][c-64]
// Block tile: 128 nodes x 128 cols, 256 threads, thread tile 8 nodes x 8 cols.
// Rows interleaved (ty + 16j) + padded sE stride -> conflict-free a-loads.
// Block 0 additionally runs the edge-index dtype probe.
// ---------------------------------------------------------------------------
__global__ void __launch_bounds__(256, 1)
precompute_kernel(const float* __restrict__ emb, const float* __restrict__ W1,
                  const float* __restrict__ b1,
                  const long long* __restrict__ eidx64, int twoE) {
    extern __shared__ float smem[];
    float* sW = smem;                 // [128][128] k-major
    float* sE = smem + 128 * 128;     // [128][SE_STRIDE] node-major, padded

    const int t = threadIdx.x;
    const int n0 = blockIdx.x * 128;

    // --- dtype probe (block 0 only): 1024 int64 words (8 KB) is in-bounds
    // under both int32 and int64 interpretations of the buffer.
    if (blockIdx.x == 0) {
        __shared__ int ok;
        if (t == 0) ok = 1;
        __syncthreads();
        int n = twoE < 1024 ? twoE : 1024;
        for (int i = t; i < n; i += 256) {
            long long v = eidx64[i];
            if (v < 0 || v >= NNODES) ok = 0;
        }
        __syncthreads();
        if (t == 0) g_is64 = ok;
    }

    // Wc loader, float4: 4096 float4s
    for (int i = t; i < 128 * 32; i += 256) {
        int k = i >> 5, c4 = i & 31;
        const float* srcp = (c4 < 16) ? (W1 + k * MLPD + c4 * 4)
                                      : (W1 + (HIDDEN + k) * MLPD + (c4 - 16) * 4);
        ((float4*)sW)[i] = *(const float4*)srcp;
    }
    // emb tile loader, float4, padded rows (row start 528 B = 16B-aligned)
    for (int i = t; i < 128 * 32; i += 256) {
        int node = i >> 5, c4 = i & 31;
        int gn = n0 + node;
        float4 v = (gn < NNODES)
            ? *(const float4*)&emb[(size_t)gn * HIDDEN + c4 * 4]
            : make_float4(0.f, 0.f, 0.f, 0.f);
        *(float4*)&sE[node * SE_STRIDE + c4 * 4] = v;
    }
    __syncthreads();

    const int tx = t & 15;   // col group: cols tx*8 .. tx*8+7
    const int ty = t >> 4;   // row base: rows ty + 16*j, j=0..7

    unsigned long long acc[8][4];
    const unsigned long long z = pk2(0.f, 0.f);
#pragma unroll
    for (int j = 0; j < 8; j++)
#pragma unroll
        for (int q = 0; q < 4; q++) acc[j][q] = z;

    for (int k0 = 0; k0 < 128; k0 += 4) {
        float4 a[8];
#pragma unroll
        for (int j = 0; j < 8; j++)
            a[j] = *(const float4*)&sE[(ty + 16 * j) * SE_STRIDE + k0];
        const float* av = (const float*)a;   // av[j*4+kk]

#pragma unroll
        for (int kk = 0; kk < 4; kk++) {
            float4 wA = *(const float4*)&sW[(k0 + kk) * 128 + tx * 8];
            float4 wB = *(const float4*)&sW[(k0 + kk) * 128 + tx * 8 + 4];
            unsigned long long p0 = pk2(wA.x, wA.y);
            unsigned long long p1 = pk2(wA.z, wA.w);
            unsigned long long p2 = pk2(wB.x, wB.y);
            unsigned long long p3 = pk2(wB.z, wB.w);
#pragma unroll
            for (int j = 0; j < 8; j++) {
                float aj = av[j * 4 + kk];
                unsigned long long aa = pk2(aj, aj);
                acc[j][0] = fma2(aa, p0, acc[j][0]);
                acc[j][1] = fma2(aa, p1, acc[j][1]);
                acc[j][2] = fma2(aa, p2, acc[j][2]);
                acc[j][3] = fma2(aa, p3, acc[j][3]);
            }
        }
    }

    // Bias: fold b1 into cols 0..63 (src half)
    float bv[8];
    if (tx < 8) {
        float4 bA = *(const float4*)&b1[tx * 8];
        float4 bB = *(const float4*)&b1[tx * 8 + 4];
        bv[0] = bA.x; bv[1] = bA.y; bv[2] = bA.z; bv[3] = bA.w;
        bv[4] = bB.x; bv[5] = bB.y; bv[6] = bB.z; bv[7] = bB.w;
    } else {
#pragma unroll
        for (int q = 0; q < 8; q++) bv[q] = 0.f;
    }

#pragma unroll
    for (int j = 0; j < 8; j++) {
        int gn = n0 + ty + 16 * j;
        if (gn < NNODES) {
            float v[8];
            upk2(acc[j][0], v[0], v[1]);
            upk2(acc[j][1], v[2], v[3]);
            upk2(acc[j][2], v[4], v[5]);
            upk2(acc[j][3], v[6], v[7]);
            float4 o0 = make_float4(v[0] + bv[0], v[1] + bv[1], v[2] + bv[2], v[3] + bv[3]);
            float4 o1 = make_float4(v[4] + bv[4], v[5] + bv[5], v[6] + bv[6], v[7] + bv[7]);
            float* dst = &g_T[(size_t)gn * HIDDEN + tx * 8];
            *(float4*)dst = o0;
            *(float4*)(dst + 4) = o1;
        }
    }
}

// ---------------------------------------------------------------------------
// Kernel 2: per edge  logit = W2 . relu(T[src][0:64] + T[dst][64:128]) + b2
// 8 threads per edge. Lane l handles cols {4l..4l+3} u {32+4l..32+4l+3} so
// every gather instruction is 8 lanes x 16 B contiguous = one 128-B line.
// ---------------------------------------------------------------------------
__global__ void __launch_bounds__(512)
edge_kernel(const void* __restrict__ eidx_raw,
            const float* __restrict__ W2, const float* __restrict__ b2,
            float* __restrict__ out, int E) {
    __shared__ float sW2[MLPD];
    __shared__ float sB2;
    const int t = threadIdx.x;
    if (t < MLPD) sW2[t] = W2[t];
    else if (t == MLPD) sB2 = *b2;
    __syncthreads();

    const int lane8 = t & 7;
    const int e = blockIdx.x * 64 + (t >> 3);
    if (e >= E) return;

    int offS, offD;
    if (g_is64) {
        const long long* p = (const long long*)eidx_raw;
        offS = (int)p[e] * HIDDEN;
        offD = (int)p[(size_t)E + e] * HIDDEN + MLPD;
    } else {
        const int* p = (const int*)eidx_raw;
        offS = p[e] * HIDDEN;
        offD = p[E + e] * HIDDEN + MLPD;
    }

    const int c0i = lane8 * 4;        // cols 4l..4l+3
    const int c1i = 32 + lane8 * 4;   // cols 32+4l..32+4l+3
    float4 a0 = *(const float4*)&g_T[offS + c0i];
    float4 a1 = *(const float4*)&g_T[offS + c1i];
    float4 d0 = *(const float4*)&g_T[offD + c0i];
    float4 d1 = *(const float4*)&g_T[offD + c1i];
    float4 w0 = *(const float4*)&sW2[c0i];
    float4 w1 = *(const float4*)&sW2[c1i];

    float h0 = fmaxf(a0.x + d0.x, 0.0f);
    float h1 = fmaxf(a0.y + d0.y, 0.0f);
    float h2 = fmaxf(a0.z + d0.z, 0.0f);
    float h3 = fmaxf(a0.w + d0.w, 0.0f);
    float h4 = fmaxf(a1.x + d1.x, 0.0f);
    float h5 = fmaxf(a1.y + d1.y, 0.0f);
    float h6 = fmaxf(a1.z + d1.z, 0.0f);
    float h7 = fmaxf(a1.w + d1.w, 0.0f);
    float sum = h0 * w0.x + h1 * w0.y + h2 * w0.z + h3 * w0.w
              + h4 * w1.x + h5 * w1.y + h6 * w1.z + h7 * w1.w;

    sum += __shfl_down_sync(0xffffffffu, sum, 4, 8);
    sum += __shfl_down_sync(0xffffffffu, sum, 2, 8);
    sum += __shfl_down_sync(0xffffffffu, sum, 1, 8);

    if (lane8 == 0) out[e] = sum + sB2;
}

// ---------------------------------------------------------------------------
extern "C" void kernel_launch(void* const* d_in, const int* in_sizes, int n_in,
                              void* d_out, int out_size) {
    const float* node_emb = (const float*)d_in[0];
    const void*  eidx     = d_in[1];
    const float* W1       = (const float*)d_in[2];
    const float* b1       = (const float*)d_in[3];
    const float* W2       = (const float*)d_in[4];
    const float* b2       = (const float*)d_in[5];
    float*       out      = (float*)d_out;

    const int twoE = in_sizes[1];
    const int E = twoE / 2;

    const int smem = (128 * 128 + 128 * SE_STRIDE) * (int)sizeof(float);  // 130 KB
    cudaFuncSetAttribute(precompute_kernel,
                         cudaFuncAttributeMaxDynamicSharedMemorySize, smem);

    precompute_kernel<<<(NNODES + 127) / 128, 256, smem>>>(
        node_emb, W1, b1, (const long long*)eidx, twoE);
    edge_kernel<<<(E + 63) / 64, 512>>>(eidx, W2, b2, out, E);
}

// round 8
// speedup vs baseline: 1.1985x; 1.1985x over previous
#include <cuda_runtime.h>
#include <cuda_bf16.h>
#include <cstdint>

#define NNODES 50000
#define HIDDEN 128
#define MLPD   64
#define SA 136   // padded bf16 row stride: 8 rows x 4-bank steps tile all 32 banks

// Per-node precomputed table:
//   T[n][0:64]   = emb[n] @ W1[0:128,:]  + b1   (src half, bias folded in)
//   T[n][64:128] = emb[n] @ W1[128:256,:]       (dst half)
__device__ float g_T[(size_t)NNODES * HIDDEN];
__device__ int g_is64;   // 1 if edge_index buffer is int64, 0 if int32

__device__ __forceinline__ uint32_t pkbf(__nv_bfloat16 a, __nv_bfloat16 b) {
    __nv_bfloat162 t = __halves2bfloat162(a, b);
    return *reinterpret_cast<uint32_t*>(&t);
}
__device__ __forceinline__ uint32_t smem_u32(const void* p) {
    return (uint32_t)__cvta_generic_to_shared(p);
}
__device__ __forceinline__ void ldsm_x4(uint32_t& r0, uint32_t& r1,
                                        uint32_t& r2, uint32_t& r3, uint32_t addr) {
    asm volatile("ldmatrix.sync.aligned.m8n8.x4.shared.b16 {%0,%1,%2,%3}, [%4];"
                 : "=r"(r0), "=r"(r1), "=r"(r2), "=r"(r3) : "r"(addr));
}
__device__ __forceinline__ void mma16816(float* d, const uint32_t* a, const uint32_t* b) {
    asm volatile(
        "mma.sync.aligned.m16n8k16.row.col.f32.bf16.bf16.f32 "
        "{%0,%1,%2,%3}, {%4,%5,%6,%7}, {%8,%9}, {%0,%1,%2,%3};"
        : "+f"(d[0]), "+f"(d[1]), "+f"(d[2]), "+f"(d[3])
        : "r"(a[0]), "r"(a[1]), "r"(a[2]), "r"(a[3]), "r"(b[0]), "r"(b[1]));
}

// ---------------------------------------------------------------------------
// Kernel 1: T = emb @ Wc (+b1 on cols 0..63) via bf16 3-GEMM split on HMMA.
//   Wc[k][c] = (c<64) ? W1[k][c] : W1[128+k][c-64]
//   T ≈ Eh@Wh + Eh@Wl + El@Wh   (El@Wl dropped, ~2^-18 relative)
// Block: 128 nodes x 128 cols, 256 threads = 8 warps (4m x 2n).
// Block 0 additionally runs the edge-index dtype probe.
// ---------------------------------------------------------------------------
__global__ void __launch_bounds__(256, 1)
precompute_kernel(const float* __restrict__ emb, const float* __restrict__ W1,
                  const float* __restrict__ b1,
                  const long long* __restrict__ eidx64, int twoE) {
    extern __shared__ char smem[];
    __nv_bfloat16* sAh = (__nv_bfloat16*)smem;           // [128][SA]
    __nv_bfloat16* sAl = sAh + 128 * SA;
    __nv_bfloat16* sBh = sAl + 128 * SA;                 // [c=128][SA] (k contiguous)
    __nv_bfloat16* sBl = sBh + 128 * SA;

    const int t = threadIdx.x;
    const int n0 = blockIdx.x * 128;

    // --- dtype probe (block 0 only): 1024 int64 words (8 KB) is in-bounds
    // under both int32 and int64 interpretations of the buffer.
    if (blockIdx.x == 0) {
        __shared__ int ok;
        if (t == 0) ok = 1;
        __syncthreads();
        int n = twoE < 1024 ? twoE : 1024;
        for (int i = t; i < n; i += 256) {
            long long v = eidx64[i];
            if (v < 0 || v >= NNODES) ok = 0;
        }
        __syncthreads();
        if (t == 0) g_is64 = ok;
    }

    // A loader: emb tile -> bf16 hi/lo, rows node-major, k contiguous
    for (int i = t; i < 128 * 32; i += 256) {
        int row = i >> 5, c4 = i & 31;
        int gn = n0 + row;
        float4 v = (gn < NNODES)
            ? *(const float4*)&emb[(size_t)gn * HIDDEN + c4 * 4]
            : make_float4(0.f, 0.f, 0.f, 0.f);
        __nv_bfloat16 hx = __float2bfloat16(v.x), hy = __float2bfloat16(v.y);
        __nv_bfloat16 hz = __float2bfloat16(v.z), hw = __float2bfloat16(v.w);
        __nv_bfloat16 lx = __float2bfloat16(v.x - __bfloat162float(hx));
        __nv_bfloat16 ly = __float2bfloat16(v.y - __bfloat162float(hy));
        __nv_bfloat16 lz = __float2bfloat16(v.z - __bfloat162float(hz));
        __nv_bfloat16 lw = __float2bfloat16(v.w - __bfloat162float(hw));
        *(uint2*)&sAh[row * SA + c4 * 4] = make_uint2(pkbf(hx, hy), pkbf(hz, hw));
        *(uint2*)&sAl[row * SA + c4 * 4] = make_uint2(pkbf(lx, ly), pkbf(lz, lw));
    }
    // B loader: Wc transposed to [c][k] (k contiguous), coalesced global reads
    for (int i = t; i < 128 * 128; i += 256) {
        int k = i >> 7, c = i & 127;
        float w = (c < MLPD) ? W1[k * MLPD + c] : W1[(HIDDEN + k) * MLPD + (c - MLPD)];
        __nv_bfloat16 h = __float2bfloat16(w);
        __nv_bfloat16 l = __float2bfloat16(w - __bfloat162float(h));
        sBh[c * SA + k] = h;
        sBl[c * SA + k] = l;
    }
    __syncthreads();

    const int lane = t & 31;
    const int wid = t >> 5;
    const int wm = wid & 3;   // rows wm*32 .. +32
    const int wn = wid >> 2;  // cols wn*64 .. +64

    // ldmatrix lane address components
    const int aRow = lane & 15, aKh = (lane >> 4) * 8;
    const int bN = (lane & 7) + ((lane >> 4) << 3), bKh = ((lane >> 3) & 1) * 8;

    float acc[2][8][4];
#pragma unroll
    for (int tm = 0; tm < 2; tm++)
#pragma unroll
        for (int tn = 0; tn < 8; tn++)
#pragma unroll
            for (int q = 0; q < 4; q++) acc[tm][tn][q] = 0.f;

#pragma unroll
    for (int pass = 0; pass < 3; pass++) {
        const __nv_bfloat16* pA = (pass == 2) ? sAl : sAh;
        const __nv_bfloat16* pB = (pass == 1) ? sBl : sBh;
#pragma unroll
        for (int k0 = 0; k0 < 128; k0 += 16) {
            uint32_t a[2][4], b[8][2];
#pragma unroll
            for (int tm = 0; tm < 2; tm++) {
                uint32_t ad = smem_u32(&pA[(wm * 32 + tm * 16 + aRow) * SA + k0 + aKh]);
                ldsm_x4(a[tm][0], a[tm][1], a[tm][2], a[tm][3], ad);
            }
#pragma unroll
            for (int tp = 0; tp < 4; tp++) {
                uint32_t bd = smem_u32(&pB[(wn * 64 + tp * 16 + bN) * SA + k0 + bKh]);
                ldsm_x4(b[2 * tp][0], b[2 * tp][1], b[2 * tp + 1][0], b[2 * tp + 1][1], bd);
            }
#pragma unroll
            for (int tm = 0; tm < 2; tm++)
#pragma unroll
                for (int tn = 0; tn < 8; tn++)
                    mma16816(acc[tm][tn], a[tm], b[tn]);
        }
    }

    // Epilogue: add b1 on cols<64, store fp32 to g_T
    const int g = lane >> 2, tig = lane & 3;
#pragma unroll
    for (int tm = 0; tm < 2; tm++) {
#pragma unroll
        for (int tn = 0; tn < 8; tn++) {
            int col = wn * 64 + tn * 8 + 2 * tig;
            float bx = 0.f, by = 0.f;
            if (wn == 0) { bx = b1[col]; by = b1[col + 1]; }
            int row0 = n0 + wm * 32 + tm * 16 + g;
            if (row0 < NNODES) {
                float2 v = make_float2(acc[tm][tn][0] + bx, acc[tm][tn][1] + by);
                *(float2*)&g_T[(size_t)row0 * HIDDEN + col] = v;
            }
            int row1 = row0 + 8;
            if (row1 < NNODES) {
                float2 v = make_float2(acc[tm][tn][2] + bx, acc[tm][tn][3] + by);
                *(float2*)&g_T[(size_t)row1 * HIDDEN + col] = v;
            }
        }
    }
}

// ---------------------------------------------------------------------------
// Kernel 2: per edge  logit = W2 . relu(T[src][0:64] + T[dst][64:128]) + b2
// 8 threads per edge. Lane l handles cols {4l..4l+3} u {32+4l..32+4l+3} so
// every gather instruction is 8 lanes x 16 B contiguous = one 128-B line.
// ---------------------------------------------------------------------------
__global__ void __launch_bounds__(512)
edge_kernel(const void* __restrict__ eidx_raw,
            const float* __restrict__ W2, const float* __restrict__ b2,
            float* __restrict__ out, int E) {
    __shared__ float sW2[MLPD];
    __shared__ float sB2;
    const int t = threadIdx.x;
    if (t < MLPD) sW2[t] = W2[t];
    else if (t == MLPD) sB2 = *b2;
    __syncthreads();

    const int lane8 = t & 7;
    const int e = blockIdx.x * 64 + (t >> 3);
    if (e >= E) return;

    int offS, offD;
    if (g_is64) {
        const long long* p = (const long long*)eidx_raw;
        offS = (int)p[e] * HIDDEN;
        offD = (int)p[(size_t)E + e] * HIDDEN + MLPD;
    } else {
        const int* p = (const int*)eidx_raw;
        offS = p[e] * HIDDEN;
        offD = p[E + e] * HIDDEN + MLPD;
    }

    const int c0i = lane8 * 4;        // cols 4l..4l+3
    const int c1i = 32 + lane8 * 4;   // cols 32+4l..32+4l+3
    float4 a0 = *(const float4*)&g_T[offS + c0i];
    float4 a1 = *(const float4*)&g_T[offS + c1i];
    float4 d0 = *(const float4*)&g_T[offD + c0i];
    float4 d1 = *(const float4*)&g_T[offD + c1i];
    float4 w0 = *(const float4*)&sW2[c0i];
    float4 w1 = *(const float4*)&sW2[c1i];

    float h0 = fmaxf(a0.x + d0.x, 0.0f);
    float h1 = fmaxf(a0.y + d0.y, 0.0f);
    float h2 = fmaxf(a0.z + d0.z, 0.0f);
    float h3 = fmaxf(a0.w + d0.w, 0.0f);
    float h4 = fmaxf(a1.x + d1.x, 0.0f);
    float h5 = fmaxf(a1.y + d1.y, 0.0f);
    float h6 = fmaxf(a1.z + d1.z, 0.0f);
    float h7 = fmaxf(a1.w + d1.w, 0.0f);
    float sum = h0 * w0.x + h1 * w0.y + h2 * w0.z + h3 * w0.w
              + h4 * w1.x + h5 * w1.y + h6 * w1.z + h7 * w1.w;

    sum += __shfl_down_sync(0xffffffffu, sum, 4, 8);
    sum += __shfl_down_sync(0xffffffffu, sum, 2, 8);
    sum += __shfl_down_sync(0xffffffffu, sum, 1, 8);

    if (lane8 == 0) out[e] = sum + sB2;
}

// ---------------------------------------------------------------------------
extern "C" void kernel_launch(void* const* d_in, const int* in_sizes, int n_in,
                              void* d_out, int out_size) {
    const float* node_emb = (const float*)d_in[0];
    const void*  eidx     = d_in[1];
    const float* W1       = (const float*)d_in[2];
    const float* b1       = (const float*)d_in[3];
    const float* W2       = (const float*)d_in[4];
    const float* b2       = (const float*)d_in[5];
    float*       out      = (float*)d_out;

    const int twoE = in_sizes[1];
    const int E = twoE / 2;

    const int smem = 4 * 128 * SA * (int)sizeof(__nv_bfloat16);  // 139264 B
    cudaFuncSetAttribute(precompute_kernel,
                         cudaFuncAttributeMaxDynamicSharedMemorySize, smem);

    precompute_kernel<<<(NNODES + 127) / 128, 256, smem>>>(
        node_emb, W1, b1, (const long long*)eidx, twoE);
    edge_kernel<<<(E + 63) / 64, 512>>>(eidx, W2, b2, out, E);
}

// round 9
// speedup vs baseline: 1.3029x; 1.0871x over previous
#include <cuda_runtime.h>
#include <cuda_bf16.h>
#include <cuda_fp16.h>
#include <cstdint>

#define NNODES 50000
#define HIDDEN 128
#define MLPD   64
#define SA 136   // padded bf16 row stride: 8-row ldmatrix steps tile all banks

// Per-node precomputed table (fp16):
//   T[n][0:64]   = emb[n] @ W1[0:128,:]  + b1   (src half, bias folded in)
//   T[n][64:128] = emb[n] @ W1[128:256,:]       (dst half)
__device__ __half g_Th[(size_t)NNODES * HIDDEN];
__device__ __nv_bfloat16 g_Wh[128 * 128];  // Wc^T hi, [c][k] k-contiguous
__device__ __nv_bfloat16 g_Wl[128 * 128];  // Wc^T lo
__device__ int g_is64;   // 1 if edge_index buffer is int64, 0 if int32

__device__ __forceinline__ uint32_t pkbf(__nv_bfloat16 a, __nv_bfloat16 b) {
    __nv_bfloat162 t = __halves2bfloat162(a, b);
    return *reinterpret_cast<uint32_t*>(&t);
}
__device__ __forceinline__ uint32_t smem_u32(const void* p) {
    return (uint32_t)__cvta_generic_to_shared(p);
}
__device__ __forceinline__ void ldsm_x4(uint32_t& r0, uint32_t& r1,
                                        uint32_t& r2, uint32_t& r3, uint32_t addr) {
    asm volatile("ldmatrix.sync.aligned.m8n8.x4.shared.b16 {%0,%1,%2,%3}, [%4];"
                 : "=r"(r0), "=r"(r1), "=r"(r2), "=r"(r3) : "r"(addr));
}
__device__ __forceinline__ void mma16816(float* d, const uint32_t* a, const uint32_t* b) {
    asm volatile(
        "mma.sync.aligned.m16n8k16.row.col.f32.bf16.bf16.f32 "
        "{%0,%1,%2,%3}, {%4,%5,%6,%7}, {%8,%9}, {%0,%1,%2,%3};"
        : "+f"(d[0]), "+f"(d[1]), "+f"(d[2]), "+f"(d[3])
        : "r"(a[0]), "r"(a[1]), "r"(a[2]), "r"(a[3]), "r"(b[0]), "r"(b[1]));
}

// ---------------------------------------------------------------------------
// Kernel 0: convert Wc = [W1 top | W1 bottom] to bf16 hi/lo, transposed [c][k].
//   Wc[k][c] = (c<64) ? W1[k][c] : W1[128+k][c-64]
// Mapping: thread handles (c, k) with k fastest -> coalesced stores.
// ---------------------------------------------------------------------------
__global__ void wconv_kernel(const float* __restrict__ W1) {
    int i = blockIdx.x * 256 + threadIdx.x;   // 0 .. 16383
    int c = i >> 7, k = i & 127;
    float w = (c < MLPD) ? W1[k * MLPD + c] : W1[(HIDDEN + k) * MLPD + (c - MLPD)];
    __nv_bfloat16 h = __float2bfloat16(w);
    g_Wh[c * 128 + k] = h;
    g_Wl[c * 128 + k] = __float2bfloat16(w - __bfloat162float(h));
}

// ---------------------------------------------------------------------------
// Kernel 1: T = emb @ Wc (+b1 on cols 0..63) via bf16 3-GEMM split on HMMA.
//   T ≈ Eh@Wh + Eh@Wl + El@Wh   (El@Wl dropped, ~2^-18 relative)
// Block: 128 nodes x 128 cols, 256 threads = 8 warps (4m x 2n). fp16 output.
// Block 0 additionally runs the edge-index dtype probe.
// ---------------------------------------------------------------------------
__global__ void __launch_bounds__(256, 1)
precompute_kernel(const float* __restrict__ emb, const float* __restrict__ b1,
                  const long long* __restrict__ eidx64, int twoE) {
    extern __shared__ char smem[];
    __nv_bfloat16* sAh = (__nv_bfloat16*)smem;           // [128][SA]
    __nv_bfloat16* sAl = sAh + 128 * SA;
    __nv_bfloat16* sBh = sAl + 128 * SA;                 // [c=128][SA] (k contiguous)
    __nv_bfloat16* sBl = sBh + 128 * SA;

    const int t = threadIdx.x;
    const int n0 = blockIdx.x * 128;

    // --- dtype probe (block 0 only): 1024 int64 words (8 KB) is in-bounds
    // under both int32 and int64 interpretations of the buffer.
    if (blockIdx.x == 0) {
        __shared__ int ok;
        if (t == 0) ok = 1;
        __syncthreads();
        int n = twoE < 1024 ? twoE : 1024;
        for (int i = t; i < n; i += 256) {
            long long v = eidx64[i];
            if (v < 0 || v >= NNODES) ok = 0;
        }
        __syncthreads();
        if (t == 0) g_is64 = ok;
    }

    // A loader: emb tile -> bf16 hi/lo, rows node-major, k contiguous
    for (int i = t; i < 128 * 32; i += 256) {
        int row = i >> 5, c4 = i & 31;
        int gn = n0 + row;
        float4 v = (gn < NNODES)
            ? *(const float4*)&emb[(size_t)gn * HIDDEN + c4 * 4]
            : make_float4(0.f, 0.f, 0.f, 0.f);
        __nv_bfloat16 hx = __float2bfloat16(v.x), hy = __float2bfloat16(v.y);
        __nv_bfloat16 hz = __float2bfloat16(v.z), hw = __float2bfloat16(v.w);
        __nv_bfloat16 lx = __float2bfloat16(v.x - __bfloat162float(hx));
        __nv_bfloat16 ly = __float2bfloat16(v.y - __bfloat162float(hy));
        __nv_bfloat16 lz = __float2bfloat16(v.z - __bfloat162float(hz));
        __nv_bfloat16 lw = __float2bfloat16(v.w - __bfloat162float(hw));
        *(uint2*)&sAh[row * SA + c4 * 4] = make_uint2(pkbf(hx, hy), pkbf(hz, hw));
        *(uint2*)&sAl[row * SA + c4 * 4] = make_uint2(pkbf(lx, ly), pkbf(lz, lw));
    }
    // B loader: vectorized copy of pre-converted g_Wh/g_Wl into padded smem
    for (int i = t; i < 128 * 16; i += 256) {   // 2048 uint4 per array
        int c = i >> 4, q = i & 15;
        *(uint4*)&sBh[c * SA + q * 8] = *(const uint4*)&g_Wh[c * 128 + q * 8];
        *(uint4*)&sBl[c * SA + q * 8] = *(const uint4*)&g_Wl[c * 128 + q * 8];
    }
    __syncthreads();

    const int lane = t & 31;
    const int wid = t >> 5;
    const int wm = wid & 3;   // rows wm*32 .. +32
    const int wn = wid >> 2;  // cols wn*64 .. +64

    const int aRow = lane & 15, aKh = (lane >> 4) * 8;
    const int bN = (lane & 7) + ((lane >> 4) << 3), bKh = ((lane >> 3) & 1) * 8;

    float acc[2][8][4];
#pragma unroll
    for (int tm = 0; tm < 2; tm++)
#pragma unroll
        for (int tn = 0; tn < 8; tn++)
#pragma unroll
            for (int q = 0; q < 4; q++) acc[tm][tn][q] = 0.f;

#pragma unroll
    for (int pass = 0; pass < 3; pass++) {
        const __nv_bfloat16* pA = (pass == 2) ? sAl : sAh;
        const __nv_bfloat16* pB = (pass == 1) ? sBl : sBh;
#pragma unroll
        for (int k0 = 0; k0 < 128; k0 += 16) {
            uint32_t a[2][4], b[8][2];
#pragma unroll
            for (int tm = 0; tm < 2; tm++) {
                uint32_t ad = smem_u32(&pA[(wm * 32 + tm * 16 + aRow) * SA + k0 + aKh]);
                ldsm_x4(a[tm][0], a[tm][1], a[tm][2], a[tm][3], ad);
            }
#pragma unroll
            for (int tp = 0; tp < 4; tp++) {
                uint32_t bd = smem_u32(&pB[(wn * 64 + tp * 16 + bN) * SA + k0 + bKh]);
                ldsm_x4(b[2 * tp][0], b[2 * tp][1], b[2 * tp + 1][0], b[2 * tp + 1][1], bd);
            }
#pragma unroll
            for (int tm = 0; tm < 2; tm++)
#pragma unroll
                for (int tn = 0; tn < 8; tn++)
                    mma16816(acc[tm][tn], a[tm], b[tn]);
        }
    }

    // Epilogue: add b1 on cols<64, store fp16 (half2) to g_Th
    const int g = lane >> 2, tig = lane & 3;
#pragma unroll
    for (int tm = 0; tm < 2; tm++) {
#pragma unroll
        for (int tn = 0; tn < 8; tn++) {
            int col = wn * 64 + tn * 8 + 2 * tig;
            float bx = 0.f, by = 0.f;
            if (wn == 0) { bx = b1[col]; by = b1[col + 1]; }
            int row0 = n0 + wm * 32 + tm * 16 + g;
            if (row0 < NNODES) {
                __half2 v = __floats2half2_rn(acc[tm][tn][0] + bx, acc[tm][tn][1] + by);
                *(__half2*)&g_Th[(size_t)row0 * HIDDEN + col] = v;
            }
            int row1 = row0 + 8;
            if (row1 < NNODES) {
                __half2 v = __floats2half2_rn(acc[tm][tn][2] + bx, acc[tm][tn][3] + by);
                *(__half2*)&g_Th[(size_t)row1 * HIDDEN + col] = v;
            }
        }
    }
}

// ---------------------------------------------------------------------------
// Kernel 2: per edge  logit = W2 . relu(T[src][0:64] + T[dst][64:128]) + b2
// 8 threads per edge; lane l covers cols 8l..8l+7 (16 B fp16). Each gather is
// 8 lanes x 16 B contiguous = ONE 128-B line per edge half.
// ---------------------------------------------------------------------------
__global__ void __launch_bounds__(512)
edge_kernel(const void* __restrict__ eidx_raw,
            const float* __restrict__ W2, const float* __restrict__ b2,
            float* __restrict__ out, int E) {
    __shared__ float sW2[MLPD];
    __shared__ float sB2;
    const int t = threadIdx.x;
    if (t < MLPD) sW2[t] = W2[t];
    else if (t == MLPD) sB2 = *b2;
    __syncthreads();

    const int lane8 = t & 7;
    const int e = blockIdx.x * 64 + (t >> 3);
    if (e >= E) return;

    int offS, offD;
    if (g_is64) {
        const long long* p = (const long long*)eidx_raw;
        offS = (int)p[e] * HIDDEN;
        offD = (int)p[(size_t)E + e] * HIDDEN + MLPD;
    } else {
        const int* p = (const int*)eidx_raw;
        offS = p[e] * HIDDEN;
        offD = p[E + e] * HIDDEN + MLPD;
    }

    uint4 sa = *(const uint4*)&g_Th[offS + lane8 * 8];
    uint4 da = *(const uint4*)&g_Th[offD + lane8 * 8];
    const __half2* sh = (const __half2*)&sa;
    const __half2* dh = (const __half2*)&da;

    float4 w0 = *(const float4*)&sW2[lane8 * 8];
    float4 w1 = *(const float4*)&sW2[lane8 * 8 + 4];

    float2 s0 = __half22float2(sh[0]), s1 = __half22float2(sh[1]);
    float2 s2 = __half22float2(sh[2]), s3 = __half22float2(sh[3]);
    float2 d0 = __half22float2(dh[0]), d1 = __half22float2(dh[1]);
    float2 d2 = __half22float2(dh[2]), d3 = __half22float2(dh[3]);

    float h0 = fmaxf(s0.x + d0.x, 0.0f);
    float h1 = fmaxf(s0.y + d0.y, 0.0f);
    float h2 = fmaxf(s1.x + d1.x, 0.0f);
    float h3 = fmaxf(s1.y + d1.y, 0.0f);
    float h4 = fmaxf(s2.x + d2.x, 0.0f);
    float h5 = fmaxf(s2.y + d2.y, 0.0f);
    float h6 = fmaxf(s3.x + d3.x, 0.0f);
    float h7 = fmaxf(s3.y + d3.y, 0.0f);
    float sum = h0 * w0.x + h1 * w0.y + h2 * w0.z + h3 * w0.w
              + h4 * w1.x + h5 * w1.y + h6 * w1.z + h7 * w1.w;

    sum += __shfl_down_sync(0xffffffffu, sum, 4, 8);
    sum += __shfl_down_sync(0xffffffffu, sum, 2, 8);
    sum += __shfl_down_sync(0xffffffffu, sum, 1, 8);

    if (lane8 == 0) out[e] = sum + sB2;
}

// ---------------------------------------------------------------------------
extern "C" void kernel_launch(void* const* d_in, const int* in_sizes, int n_in,
                              void* d_out, int out_size) {
    const float* node_emb = (const float*)d_in[0];
    const void*  eidx     = d_in[1];
    const float* W1       = (const float*)d_in[2];
    const float* b1       = (const float*)d_in[3];
    const float* W2       = (const float*)d_in[4];
    const float* b2       = (const float*)d_in[5];
    float*       out      = (float*)d_out;

    const int twoE = in_sizes[1];
    const int E = twoE / 2;

    const int smem = 4 * 128 * SA * (int)sizeof(__nv_bfloat16);  // 139264 B
    cudaFuncSetAttribute(precompute_kernel,
                         cudaFuncAttributeMaxDynamicSharedMemorySize, smem);

    wconv_kernel<<<64, 256>>>(W1);
    precompute_kernel<<<(NNODES + 127) / 128, 256, smem>>>(
        node_emb, b1, (const long long*)eidx, twoE);
    edge_kernel<<<(E + 63) / 64, 512>>>(eidx, W2, b2, out, E);
}